// round 15
// baseline (speedup 1.0000x reference)
#include <cuda_runtime.h>
#include <cuda_bf16.h>
#include <math.h>
#include <stdint.h>

// ---------------- problem constants ----------------
#define BT_   1024
#define CH_   3
#define AW_   64
#define BH_   64
#define NF_   16
#define HD_   1024
#define IN_   768
#define GATE_ 4096
#define TSTEPS_ 16

// ---------------- persistent scratch ----------------
__device__ float g_h[BT_ * HD_];
__device__ float g_c[BT_ * HD_];
__device__ float g_t[BT_ * HD_];

// pre-split bf16 activations
__device__ __nv_bfloat16 g_r_hi[BT_ * IN_];
__device__ __nv_bfloat16 g_r_lo[BT_ * IN_];
__device__ __nv_bfloat16 g_h_hi[BT_ * HD_];
__device__ __nv_bfloat16 g_h_lo[BT_ * HD_];

// pre-split bf16 weights (gate-interleaved row order) + fused bias
__device__ __nv_bfloat16 g_Wih_hi[GATE_ * IN_];
__device__ __nv_bfloat16 g_Wih_lo[GATE_ * IN_];
__device__ __nv_bfloat16 g_Whh_hi[GATE_ * HD_];
__device__ __nv_bfloat16 g_Whh_lo[GATE_ * HD_];
__device__ float g_bias[GATE_];

// ---------------- helpers ----------------
__device__ __forceinline__ uint32_t smem_to_u32(const void* p) {
    uint32_t a;
    asm("{ .reg .u64 t; cvta.to.shared.u64 t, %1; cvt.u32.u64 %0, t; }" : "=r"(a) : "l"(p));
    return a;
}
__device__ __forceinline__ void ldsm4(uint32_t* r, uint32_t addr) {
    asm volatile("ldmatrix.sync.aligned.m8n8.x4.shared.b16 {%0,%1,%2,%3}, [%4];"
        : "=r"(r[0]), "=r"(r[1]), "=r"(r[2]), "=r"(r[3]) : "r"(addr));
}
__device__ __forceinline__ void mma_bf16(float* d, const uint32_t* a, const uint32_t* b) {
    asm volatile("mma.sync.aligned.m16n8k16.row.col.f32.bf16.bf16.f32 "
        "{%0,%1,%2,%3}, {%4,%5,%6,%7}, {%8,%9}, {%0,%1,%2,%3};"
        : "+f"(d[0]), "+f"(d[1]), "+f"(d[2]), "+f"(d[3])
        : "r"(a[0]), "r"(a[1]), "r"(a[2]), "r"(a[3]), "r"(b[0]), "r"(b[1]));
}
__device__ __forceinline__ void cpa16(uint32_t dst, const void* src) {
    asm volatile("cp.async.cg.shared.global [%0], [%1], 16;" :: "r"(dst), "l"(src));
}
#define CP_COMMIT() asm volatile("cp.async.commit_group;")
#define CP_WAIT(n)  asm volatile("cp.async.wait_group %0;" :: "n"(n))

__device__ __forceinline__ void splitf(float v, __nv_bfloat16& hi, __nv_bfloat16& lo) {
    hi = __float2bfloat16_rn(v);
    lo = __float2bfloat16_rn(v - __bfloat162float(hi));
}
__device__ __forceinline__ float sigm(float v) { return 1.f / (1.f + expf(-v)); }

// row reorder: orig row rho -> blk*256 + gate*64 + jw
__device__ __forceinline__ int remap_row(int rho) {
    int gate = rho >> 10;
    int rem  = rho & 1023;
    return (rem >> 6) * 256 + gate * 64 + (rem & 63);
}

// ---------------- weight prep (split + reorder) ----------------
__global__ void prep_kernel(const float* __restrict__ W_ih, const float* __restrict__ W_hh,
                            const float* __restrict__ b_ih, const float* __restrict__ b_hh) {
    const int T1 = GATE_ * IN_;
    const int T2 = GATE_ * HD_;
    int i = blockIdx.x * blockDim.x + threadIdx.x;
    if (i < T1) {
        int rho = i / IN_, k = i - rho * IN_;
        int ni = remap_row(rho) * IN_ + k;
        splitf(W_ih[i], g_Wih_hi[ni], g_Wih_lo[ni]);
    } else if (i < T1 + T2) {
        int j = i - T1;
        int rho = j >> 10, k = j & 1023;
        int ni = (remap_row(rho) << 10) + k;
        splitf(W_hh[j], g_Whh_hi[ni], g_Whh_lo[ni]);
    } else if (i < T1 + T2 + GATE_) {
        int rho = i - T1 - T2;
        g_bias[remap_row(rho)] = b_ih[rho] + b_hh[rho];
    }
}

// ---------------- fused att + filterbank + glimpse (512 threads) ----------------
// one block per batch element
#define FX_STRIDE 66
#define TMP_STRIDE 33
__global__ __launch_bounds__(512)
void att_glimpse_kernel(const float* __restrict__ x,
                        const float* __restrict__ h,
                        const float* __restrict__ W_att,
                        const float* __restrict__ b_att) {
    const int b   = blockIdx.x;
    const int tid = threadIdx.x;
    const int lane = tid & 31;
    const int wid = tid >> 5;

    __shared__ float  sFy[NF_ * BH_];
    __shared__ float  sFxp[NF_ * FX_STRIDE];
    __shared__ float2 sImg2[BH_ * 32];
    __shared__ float2 sTmp2[NF_ * TMP_STRIDE];
    __shared__ float  red[5][16];
    __shared__ float  params[5];
    __shared__ float  rnorm[16];

    // ---- attention params: p = h[b] @ W_att.T + b_att ----
    {
        float a0 = 0.f, a1 = 0.f, a2 = 0.f, a3 = 0.f, a4 = 0.f;
        const float* hb = h + b * HD_;
        #pragma unroll
        for (int s = 0; s < 2; s++) {
            int k = tid + s * 512;
            float hv = hb[k];
            a0 += hv * W_att[0 * HD_ + k];
            a1 += hv * W_att[1 * HD_ + k];
            a2 += hv * W_att[2 * HD_ + k];
            a3 += hv * W_att[3 * HD_ + k];
            a4 += hv * W_att[4 * HD_ + k];
        }
        #pragma unroll
        for (int off = 16; off; off >>= 1) {
            a0 += __shfl_down_sync(0xffffffffu, a0, off);
            a1 += __shfl_down_sync(0xffffffffu, a1, off);
            a2 += __shfl_down_sync(0xffffffffu, a2, off);
            a3 += __shfl_down_sync(0xffffffffu, a3, off);
            a4 += __shfl_down_sync(0xffffffffu, a4, off);
        }
        if (lane == 0) {
            red[0][wid] = a0; red[1][wid] = a1; red[2][wid] = a2;
            red[3][wid] = a3; red[4][wid] = a4;
        }
        __syncthreads();
        if (tid < 5) {
            float s = 0.f;
            #pragma unroll
            for (int w = 0; w < 16; w++) s += red[tid][w];
            params[tid] = s + b_att[tid];
        }
        __syncthreads();
    }

    const float gx     = 32.5f * (params[0] + 1.0f);
    const float gy     = 32.5f * (params[1] + 1.0f);
    const float sigma2 = expf(params[2]);
    const float delta  = (63.0f / 15.0f) * expf(params[3]);
    const float gam    = expf(params[4]);
    const float inv2s  = 1.0f / (2.0f * sigma2);

    // ---- Fx filterbank (fast exp) ----
    for (int idx = tid; idx < NF_ * AW_; idx += 512) {
        int i = idx >> 6, a = idx & 63;
        float mu = gx + ((float)i - 8.5f) * delta;
        float d  = (float)a - mu;
        sFxp[i * FX_STRIDE + a] = __expf(-d * d * inv2s);
    }
    __syncthreads();
    if (tid < 16) {
        float s = 0.f;
        for (int a = 0; a < 64; a++) s += sFxp[tid * FX_STRIDE + a];
        rnorm[tid] = 1.0f / (s + 1e-8f);
    }
    __syncthreads();
    for (int idx = tid; idx < NF_ * AW_; idx += 512) {
        int i = idx >> 6, a = idx & 63;
        sFxp[i * FX_STRIDE + a] *= rnorm[i];
    }
    __syncthreads();

    // ---- Fy filterbank (fast exp) ----
    for (int idx = tid; idx < NF_ * BH_; idx += 512) {
        int i = idx >> 6, a = idx & 63;
        float mu = gy + ((float)i - 8.5f) * delta;
        float d  = (float)a - mu;
        sFy[idx] = __expf(-d * d * inv2s);
    }
    __syncthreads();
    if (tid < 16) {
        float s = 0.f;
        for (int a = 0; a < 64; a++) s += sFy[tid * 64 + a];
        rnorm[tid] = 1.0f / (s + 1e-8f);
    }
    __syncthreads();
    for (int idx = tid; idx < NF_ * BH_; idx += 512) {
        sFy[idx] *= rnorm[idx >> 6];
    }

    // ---- glimpse per channel ----
    const int a2 = tid & 31;      // float2 column
    const int nr = tid >> 5;      // 0..15: one n-row per thread
    const int pn = tid >> 4;      // phase-2 n (first 256 threads)
    const int pxo = tid & 15;

    for (int c = 0; c < CH_; c++) {
        __syncthreads();
        const float* xc = x + ((size_t)(b * CH_ + c)) * (BH_ * AW_);
        for (int idx = tid; idx < BH_ * 32; idx += 512)
            sImg2[idx] = reinterpret_cast<const float2*>(xc)[idx];
        __syncthreads();

        // phase 1: tmp[n][a2] = sum_y Fy[n][y] * img2[y][a2], one n-row per thread
        {
            float tx = 0.f, ty = 0.f;
            const float* fy = &sFy[nr * BH_];
            #pragma unroll 8
            for (int y = 0; y < BH_; y++) {
                float2 iv = sImg2[y * 32 + a2];
                float f = fy[y];
                tx += f * iv.x; ty += f * iv.y;
            }
            sTmp2[nr * TMP_STRIDE + a2] = make_float2(tx, ty);
        }
        __syncthreads();

        // phase 2: out[n][xo] = gamma * sum_a tmp[n][a] * Fx[xo][a] (first 256 threads)
        if (tid < 256) {
            const float2* tv = &sTmp2[pn * TMP_STRIDE];
            const float2* fv = reinterpret_cast<const float2*>(&sFxp[pxo * FX_STRIDE]);
            float s = 0.f;
            #pragma unroll 8
            for (int q = 0; q < 32; q++) {
                float2 t = tv[q];
                float2 f = fv[q];
                s += t.x * f.x + t.y * f.y;
            }
            s *= gam;
            int idx = b * IN_ + c * (NF_ * NF_) + pn * NF_ + pxo;
            __nv_bfloat16 hi, lo;
            splitf(s, hi, lo);
            g_r_hi[idx] = hi;
            g_r_lo[idx] = lo;
        }
    }
}

// ---------------- HMMA gate GEMM + fused LSTM epilogue (round-7 config) ----------------
#define KCHUNKS 28
#define LDS_ROW 144
#define A_HI 0
#define A_LO 18432
#define W_HI 36864
#define W_LO 73728
#define STAGE_BYTES 110592
#define GEMM_SMEM (2 * STAGE_BYTES)

__device__ __forceinline__ void load_chunk_async(int kt, int m0, int n0, int tid,
                                                 uint32_t stage) {
    const __nv_bfloat16 *Ah, *Al, *Wh, *Wl;
    int ldA, kk;
    if (kt < 12) { Ah = g_r_hi; Al = g_r_lo; Wh = g_Wih_hi; Wl = g_Wih_lo; ldA = IN_; kk = kt * 64; }
    else         { Ah = g_h_hi; Al = g_h_lo; Wh = g_Whh_hi; Wl = g_Whh_lo; ldA = HD_; kk = (kt - 12) * 64; }

    if (tid < 256) {
        int row = tid >> 1, hf = tid & 1;
        const __nv_bfloat16* sh = Ah + (size_t)(m0 + row) * ldA + kk + hf * 32;
        const __nv_bfloat16* sl = Al + (size_t)(m0 + row) * ldA + kk + hf * 32;
        uint32_t d = stage + A_HI + row * LDS_ROW + hf * 64;
        #pragma unroll
        for (int i = 0; i < 4; i++) {
            cpa16(d + i * 16, sh + i * 8);
            cpa16(d + (A_LO - A_HI) + i * 16, sl + i * 8);
        }
    } else {
        int t = tid - 256;
        const __nv_bfloat16* sh = Wh + (size_t)(n0 + t) * ldA + kk;
        const __nv_bfloat16* sl = Wl + (size_t)(n0 + t) * ldA + kk;
        uint32_t d = stage + W_HI + t * LDS_ROW;
        #pragma unroll
        for (int i = 0; i < 8; i++) {
            cpa16(d + i * 16, sh + i * 8);
            cpa16(d + (W_LO - W_HI) + i * 16, sl + i * 8);
        }
    }
}

__global__ __launch_bounds__(512, 1)
void gate_gemm_lstm(float* __restrict__ c_state, float* __restrict__ h_state) {
    extern __shared__ char smem[];
    const uint32_t sb = smem_to_u32(smem);
    const int tid = threadIdx.x;
    const int lane = tid & 31;
    const int wid = tid >> 5;
    const int warp_m = wid >> 2;     // 0..3
    const int warp_n = wid & 3;      // 0..3 (= gate index)
    const int nb = blockIdx.x;
    const int n0 = nb * 256;
    const int m0 = blockIdx.y * 128;

    float acc[2][8][4];
    #pragma unroll
    for (int i = 0; i < 2; i++)
        #pragma unroll
        for (int j = 0; j < 8; j++)
            #pragma unroll
            for (int k = 0; k < 4; k++) acc[i][j][k] = 0.f;

    load_chunk_async(0, m0, n0, tid, sb);
    CP_COMMIT();

    for (int kt = 0; kt < KCHUNKS; kt++) {
        const uint32_t sA = sb + (kt & 1) * STAGE_BYTES;
        if (kt + 1 < KCHUNKS) {
            load_chunk_async(kt + 1, m0, n0, tid, sb + ((kt + 1) & 1) * STAGE_BYTES);
            CP_COMMIT();
            CP_WAIT(1);
        } else {
            CP_WAIT(0);
        }
        __syncthreads();

        #pragma unroll
        for (int k16 = 0; k16 < 4; k16++) {
            uint32_t ah[2][4], al[2][4];
            #pragma unroll
            for (int mt = 0; mt < 2; mt++) {
                uint32_t row = warp_m * 32 + mt * 16 + (lane & 15);
                uint32_t ad = sA + A_HI + row * LDS_ROW + k16 * 32 + ((lane >> 4) * 16);
                ldsm4(ah[mt], ad);
                ldsm4(al[mt], ad + (A_LO - A_HI));
            }
            const uint32_t rown = warp_n * 64 + (lane & 7) + ((lane >> 4) * 8);
            const uint32_t coff = k16 * 32 + (((lane >> 3) & 1) * 16);
            #pragma unroll
            for (int g = 0; g < 4; g++) {
                uint32_t t4[4];
                ldsm4(t4, sA + W_HI + (rown + g * 16) * LDS_ROW + coff);
                #pragma unroll
                for (int mt = 0; mt < 2; mt++) {
                    mma_bf16(acc[mt][2 * g],     ah[mt], t4);
                    mma_bf16(acc[mt][2 * g + 1], ah[mt], t4 + 2);
                    mma_bf16(acc[mt][2 * g],     al[mt], t4);
                    mma_bf16(acc[mt][2 * g + 1], al[mt], t4 + 2);
                }
            }
            #pragma unroll
            for (int g = 0; g < 4; g++) {
                uint32_t t4[4];
                ldsm4(t4, sA + W_LO + (rown + g * 16) * LDS_ROW + coff);
                #pragma unroll
                for (int mt = 0; mt < 2; mt++) {
                    mma_bf16(acc[mt][2 * g],     ah[mt], t4);
                    mma_bf16(acc[mt][2 * g + 1], ah[mt], t4 + 2);
                }
            }
        }
        __syncthreads();
    }

    // ---- fused LSTM epilogue ----
    float* stg = reinterpret_cast<float*>(smem);
    const int r0 = lane >> 2;
    const int c0 = (lane & 3) * 2;

    #pragma unroll
    for (int mt = 0; mt < 2; mt++) {
        #pragma unroll
        for (int nt = 0; nt < 8; nt++) {
            int scol = warp_n * 64 + nt * 8 + c0;
            int srow = warp_m * 16 + r0;
            stg[srow * 256 + scol]           = acc[mt][nt][0];
            stg[srow * 256 + scol + 1]       = acc[mt][nt][1];
            stg[(srow + 8) * 256 + scol]     = acc[mt][nt][2];
            stg[(srow + 8) * 256 + scol + 1] = acc[mt][nt][3];
        }
        __syncthreads();

        #pragma unroll
        for (int t = 0; t < 8; t++) {
            int idx = t * 512 + tid;
            int sr = idx >> 6;
            int jw = idx & 63;
            int m  = m0 + (sr >> 4) * 32 + mt * 16 + (sr & 15);
            int j  = nb * 64 + jw;

            float ig = stg[sr * 256 + jw]        + g_bias[n0 + jw];
            float fg = stg[sr * 256 + 64 + jw]   + g_bias[n0 + 64 + jw];
            float gg = stg[sr * 256 + 128 + jw]  + g_bias[n0 + 128 + jw];
            float og = stg[sr * 256 + 192 + jw]  + g_bias[n0 + 192 + jw];

            int ci = m * HD_ + j;
            float cn = sigm(fg) * c_state[ci] + sigm(ig) * tanhf(gg);
            c_state[ci] = cn;
            float hn = sigm(og) * tanhf(cn);
            h_state[ci] = hn;
            __nv_bfloat16 hi, lo;
            splitf(hn, hi, lo);
            g_h_hi[ci] = hi;
            g_h_lo[ci] = lo;
        }
        __syncthreads();
    }
}

// ---------------- zero h and c (+ splits) ----------------
__global__ void zero_hc_kernel() {
    int i = blockIdx.x * blockDim.x + threadIdx.x;
    if (i < BT_ * HD_) {
        g_h[i] = 0.f; g_c[i] = 0.f;
        g_h_hi[i] = __float2bfloat16(0.f);
        g_h_lo[i] = __float2bfloat16(0.f);
    }
}

// ---------------- SIMT GEMM (fc0 only) ----------------
template <bool RELU>
__global__ __launch_bounds__(256, 2)
void gemm_nt(const float* __restrict__ A0, int K0, const float* __restrict__ W0,
             const float* __restrict__ bias0,
             float* __restrict__ C, int M, int Nn) {
    __shared__ float As[16][128];
    __shared__ float Bs[16][128];

    const int tid = threadIdx.x;
    const int m0  = blockIdx.y * 128;
    const int n0  = blockIdx.x * 128;
    const int tx  = tid & 15;
    const int ty  = tid >> 4;
    const int lrow = tid >> 1;
    const int lq   = (tid & 1) * 2;

    float acc[8][8];
    #pragma unroll
    for (int i = 0; i < 8; i++)
        #pragma unroll
        for (int j = 0; j < 8; j++) acc[i][j] = 0.f;

    for (int kt = 0; kt < K0; kt += 16) {
        #pragma unroll
        for (int qq = 0; qq < 2; qq++) {
            int q = lq + qq;
            float4 va = *reinterpret_cast<const float4*>(A0 + (m0 + lrow) * K0 + kt + q * 4);
            As[q * 4 + 0][lrow] = va.x;
            As[q * 4 + 1][lrow] = va.y;
            As[q * 4 + 2][lrow] = va.z;
            As[q * 4 + 3][lrow] = va.w;
            float4 vb = *reinterpret_cast<const float4*>(W0 + (n0 + lrow) * K0 + kt + q * 4);
            Bs[q * 4 + 0][lrow] = vb.x;
            Bs[q * 4 + 1][lrow] = vb.y;
            Bs[q * 4 + 2][lrow] = vb.z;
            Bs[q * 4 + 3][lrow] = vb.w;
        }
        __syncthreads();

        #pragma unroll
        for (int k = 0; k < 16; k++) {
            float ra[8], rb[8];
            #pragma unroll
            for (int i = 0; i < 8; i++) ra[i] = As[k][ty * 8 + i];
            #pragma unroll
            for (int j = 0; j < 8; j++) rb[j] = Bs[k][tx * 8 + j];
            #pragma unroll
            for (int i = 0; i < 8; i++)
                #pragma unroll
                for (int j = 0; j < 8; j++) acc[i][j] += ra[i] * rb[j];
        }
        __syncthreads();
    }

    #pragma unroll
    for (int i = 0; i < 8; i++) {
        int m = m0 + ty * 8 + i;
        #pragma unroll
        for (int jv = 0; jv < 2; jv++) {
            int n = n0 + tx * 8 + jv * 4;
            float4 v;
            float* vp = &v.x;
            #pragma unroll
            for (int u = 0; u < 4; u++) {
                float t = acc[i][jv * 4 + u] + bias0[n + u];
                if (RELU) t = fmaxf(t, 0.f);
                vp[u] = t;
            }
            *reinterpret_cast<float4*>(C + (size_t)m * Nn + n) = v;
        }
    }
}

// ---------------- final small fc ----------------
__global__ void fc_kernel(const float* __restrict__ t,
                          const float* __restrict__ W_fc,
                          const float* __restrict__ b_fc,
                          float* __restrict__ out) {
    int b    = blockIdx.x;
    int w    = threadIdx.x >> 5;
    int lane = threadIdx.x & 31;
    const float* tb = t + b * HD_;
    const float* wr = W_fc + w * HD_;
    float s = 0.f;
    for (int k = lane; k < HD_; k += 32) s += tb[k] * wr[k];
    #pragma unroll
    for (int off = 16; off; off >>= 1) s += __shfl_down_sync(0xffffffffu, s, off);
    if (lane == 0) out[b * 10 + w] = s + b_fc[w];
}

// ---------------- host launch ----------------
extern "C" void kernel_launch(void* const* d_in, const int* in_sizes, int n_in,
                              void* d_out, int out_size) {
    const float* x     = (const float*)d_in[0];
    const float* W_att = (const float*)d_in[1];
    const float* b_att = (const float*)d_in[2];
    const float* W_ih  = (const float*)d_in[3];
    const float* W_hh  = (const float*)d_in[4];
    const float* b_ih  = (const float*)d_in[5];
    const float* b_hh  = (const float*)d_in[6];
    const float* W_fc0 = (const float*)d_in[7];
    const float* b_fc0 = (const float*)d_in[8];
    const float* W_fc  = (const float*)d_in[9];
    const float* b_fc  = (const float*)d_in[10];
    float* out = (float*)d_out;

    static float *p_h = nullptr, *p_c, *p_t;
    static bool attr_done = false;
    if (!p_h) {
        cudaGetSymbolAddress((void**)&p_h, g_h);
        cudaGetSymbolAddress((void**)&p_c, g_c);
        cudaGetSymbolAddress((void**)&p_t, g_t);
    }
    if (!attr_done) {
        cudaFuncSetAttribute(gate_gemm_lstm,
                             cudaFuncAttributeMaxDynamicSharedMemorySize, GEMM_SMEM);
        attr_done = true;
    }

    {
        const int total = GATE_ * IN_ + GATE_ * HD_ + GATE_;
        prep_kernel<<<(total + 255) / 256, 256>>>(W_ih, W_hh, b_ih, b_hh);
    }

    zero_hc_kernel<<<(BT_ * HD_ + 255) / 256, 256>>>();

    for (int step = 0; step < TSTEPS_; step++) {
        att_glimpse_kernel<<<BT_, 512>>>(x, p_h, W_att, b_att);
        gate_gemm_lstm<<<dim3(GATE_ / 256, BT_ / 128), 512, GEMM_SMEM>>>(p_c, p_h);
    }

    gemm_nt<true><<<dim3(HD_ / 128, BT_ / 128), 256>>>(p_h, HD_, W_fc0, b_fc0, p_t, BT_, HD_);

    fc_kernel<<<BT_, 320>>>(p_t, W_fc, b_fc, out);
}

// round 16
// speedup vs baseline: 1.0539x; 1.0539x over previous
#include <cuda_runtime.h>
#include <cuda_bf16.h>
#include <math.h>
#include <stdint.h>

// ---------------- problem constants ----------------
#define BT_   1024
#define CH_   3
#define AW_   64
#define BH_   64
#define NF_   16
#define HD_   1024
#define IN_   768
#define GATE_ 4096
#define TSTEPS_ 16

// ---------------- persistent scratch ----------------
__device__ float g_h[BT_ * HD_];
__device__ float g_c[BT_ * HD_];
__device__ float g_t[BT_ * HD_];

// pre-split bf16 activations
__device__ __nv_bfloat16 g_r_hi[BT_ * IN_];
__device__ __nv_bfloat16 g_r_lo[BT_ * IN_];
__device__ __nv_bfloat16 g_h_hi[BT_ * HD_];
__device__ __nv_bfloat16 g_h_lo[BT_ * HD_];

// pre-split bf16 weights (gate-interleaved row order) + fused bias
__device__ __nv_bfloat16 g_Wih_hi[GATE_ * IN_];
__device__ __nv_bfloat16 g_Wih_lo[GATE_ * IN_];
__device__ __nv_bfloat16 g_Whh_hi[GATE_ * HD_];
__device__ __nv_bfloat16 g_Whh_lo[GATE_ * HD_];
__device__ float g_bias[GATE_];

// ---------------- helpers ----------------
__device__ __forceinline__ uint32_t smem_to_u32(const void* p) {
    uint32_t a;
    asm("{ .reg .u64 t; cvta.to.shared.u64 t, %1; cvt.u32.u64 %0, t; }" : "=r"(a) : "l"(p));
    return a;
}
__device__ __forceinline__ void ldsm4(uint32_t* r, uint32_t addr) {
    asm volatile("ldmatrix.sync.aligned.m8n8.x4.shared.b16 {%0,%1,%2,%3}, [%4];"
        : "=r"(r[0]), "=r"(r[1]), "=r"(r[2]), "=r"(r[3]) : "r"(addr));
}
__device__ __forceinline__ void mma_bf16(float* d, const uint32_t* a, const uint32_t* b) {
    asm volatile("mma.sync.aligned.m16n8k16.row.col.f32.bf16.bf16.f32 "
        "{%0,%1,%2,%3}, {%4,%5,%6,%7}, {%8,%9}, {%0,%1,%2,%3};"
        : "+f"(d[0]), "+f"(d[1]), "+f"(d[2]), "+f"(d[3])
        : "r"(a[0]), "r"(a[1]), "r"(a[2]), "r"(a[3]), "r"(b[0]), "r"(b[1]));
}
__device__ __forceinline__ void cpa16(uint32_t dst, const void* src) {
    asm volatile("cp.async.cg.shared.global [%0], [%1], 16;" :: "r"(dst), "l"(src));
}
#define CP_COMMIT() asm volatile("cp.async.commit_group;")
#define CP_WAIT(n)  asm volatile("cp.async.wait_group %0;" :: "n"(n))

__device__ __forceinline__ void splitf(float v, __nv_bfloat16& hi, __nv_bfloat16& lo) {
    hi = __float2bfloat16_rn(v);
    lo = __float2bfloat16_rn(v - __bfloat162float(hi));
}
// fast sigmoid/tanh via MUFU exp (rel err ~1e-7, far below split error 3e-4)
__device__ __forceinline__ float sigm_f(float v) { return 1.f / (1.f + __expf(-v)); }
__device__ __forceinline__ float tanh_f(float v) { return 2.f / (1.f + __expf(-2.f * v)) - 1.f; }
__device__ __forceinline__ float sigm(float v) { return 1.f / (1.f + expf(-v)); }

// row reorder: orig row rho -> blk*256 + gate*64 + jw
__device__ __forceinline__ int remap_row(int rho) {
    int gate = rho >> 10;
    int rem  = rho & 1023;
    return (rem >> 6) * 256 + gate * 64 + (rem & 63);
}

// ---------------- weight prep (split + reorder) ----------------
__global__ void prep_kernel(const float* __restrict__ W_ih, const float* __restrict__ W_hh,
                            const float* __restrict__ b_ih, const float* __restrict__ b_hh) {
    const int T1 = GATE_ * IN_;
    const int T2 = GATE_ * HD_;
    int i = blockIdx.x * blockDim.x + threadIdx.x;
    if (i < T1) {
        int rho = i / IN_, k = i - rho * IN_;
        int ni = remap_row(rho) * IN_ + k;
        splitf(W_ih[i], g_Wih_hi[ni], g_Wih_lo[ni]);
    } else if (i < T1 + T2) {
        int j = i - T1;
        int rho = j >> 10, k = j & 1023;
        int ni = (remap_row(rho) << 10) + k;
        splitf(W_hh[j], g_Whh_hi[ni], g_Whh_lo[ni]);
    } else if (i < T1 + T2 + GATE_) {
        int rho = i - T1 - T2;
        g_bias[remap_row(rho)] = b_ih[rho] + b_hh[rho];
    }
}

// ---------------- fused att + filterbank + glimpse (round-12 exact) ----------------
#define FX_STRIDE 66
#define TMP_STRIDE 33
__global__ __launch_bounds__(256)
void att_glimpse_kernel(const float* __restrict__ x,
                        const float* __restrict__ h,
                        const float* __restrict__ W_att,
                        const float* __restrict__ b_att) {
    const int b   = blockIdx.x;
    const int tid = threadIdx.x;
    const int lane = tid & 31;
    const int wid = tid >> 5;

    __shared__ float  sFy[NF_ * BH_];
    __shared__ float  sFxp[NF_ * FX_STRIDE];
    __shared__ float2 sImg2[BH_ * 32];
    __shared__ float2 sTmp2[NF_ * TMP_STRIDE];
    __shared__ float  red[5][8];
    __shared__ float  params[5];
    __shared__ float  rnorm[16];

    // ---- attention params: p = h[b] @ W_att.T + b_att ----
    {
        float a0 = 0.f, a1 = 0.f, a2 = 0.f, a3 = 0.f, a4 = 0.f;
        const float* hb = h + b * HD_;
        for (int k = tid; k < HD_; k += 256) {
            float hv = hb[k];
            a0 += hv * W_att[0 * HD_ + k];
            a1 += hv * W_att[1 * HD_ + k];
            a2 += hv * W_att[2 * HD_ + k];
            a3 += hv * W_att[3 * HD_ + k];
            a4 += hv * W_att[4 * HD_ + k];
        }
        #pragma unroll
        for (int off = 16; off; off >>= 1) {
            a0 += __shfl_down_sync(0xffffffffu, a0, off);
            a1 += __shfl_down_sync(0xffffffffu, a1, off);
            a2 += __shfl_down_sync(0xffffffffu, a2, off);
            a3 += __shfl_down_sync(0xffffffffu, a3, off);
            a4 += __shfl_down_sync(0xffffffffu, a4, off);
        }
        if (lane == 0) {
            red[0][wid] = a0; red[1][wid] = a1; red[2][wid] = a2;
            red[3][wid] = a3; red[4][wid] = a4;
        }
        __syncthreads();
        if (tid < 5) {
            float s = 0.f;
            #pragma unroll
            for (int w = 0; w < 8; w++) s += red[tid][w];
            params[tid] = s + b_att[tid];
        }
        __syncthreads();
    }

    const float gx     = 32.5f * (params[0] + 1.0f);
    const float gy     = 32.5f * (params[1] + 1.0f);
    const float sigma2 = expf(params[2]);
    const float delta  = (63.0f / 15.0f) * expf(params[3]);
    const float gam    = expf(params[4]);
    const float inv2s  = 1.0f / (2.0f * sigma2);

    // ---- Fx filterbank (fast exp) ----
    for (int idx = tid; idx < NF_ * AW_; idx += 256) {
        int i = idx >> 6, a = idx & 63;
        float mu = gx + ((float)i - 8.5f) * delta;
        float d  = (float)a - mu;
        sFxp[i * FX_STRIDE + a] = __expf(-d * d * inv2s);
    }
    __syncthreads();
    if (tid < 16) {
        float s = 0.f;
        for (int a = 0; a < 64; a++) s += sFxp[tid * FX_STRIDE + a];
        rnorm[tid] = 1.0f / (s + 1e-8f);
    }
    __syncthreads();
    for (int idx = tid; idx < NF_ * AW_; idx += 256) {
        int i = idx >> 6, a = idx & 63;
        sFxp[i * FX_STRIDE + a] *= rnorm[i];
    }
    __syncthreads();

    // ---- Fy filterbank (fast exp) ----
    for (int idx = tid; idx < NF_ * BH_; idx += 256) {
        int i = idx >> 6, a = idx & 63;
        float mu = gy + ((float)i - 8.5f) * delta;
        float d  = (float)a - mu;
        sFy[idx] = __expf(-d * d * inv2s);
    }
    __syncthreads();
    if (tid < 16) {
        float s = 0.f;
        for (int a = 0; a < 64; a++) s += sFy[tid * 64 + a];
        rnorm[tid] = 1.0f / (s + 1e-8f);
    }
    __syncthreads();
    for (int idx = tid; idx < NF_ * BH_; idx += 256) {
        sFy[idx] *= rnorm[idx >> 6];
    }

    // ---- glimpse per channel ----
    const int a2 = tid & 31;
    const int nb = tid >> 5;
    const int pn = tid >> 4;
    const int pxo = tid & 15;

    for (int c = 0; c < CH_; c++) {
        __syncthreads();
        const float* xc = x + ((size_t)(b * CH_ + c)) * (BH_ * AW_);
        for (int idx = tid; idx < BH_ * 32; idx += 256)
            sImg2[idx] = reinterpret_cast<const float2*>(xc)[idx];
        __syncthreads();

        // phase 1: tmp[n][a2] = sum_y Fy[n][y] * img2[y][a2], 2 n-rows per thread
        {
            float t0x = 0.f, t0y = 0.f, t1x = 0.f, t1y = 0.f;
            const float* fy0 = &sFy[nb * BH_];
            const float* fy1 = &sFy[(nb + 8) * BH_];
            #pragma unroll 8
            for (int y = 0; y < BH_; y++) {
                float2 iv = sImg2[y * 32 + a2];
                float f0 = fy0[y];
                float f1 = fy1[y];
                t0x += f0 * iv.x; t0y += f0 * iv.y;
                t1x += f1 * iv.x; t1y += f1 * iv.y;
            }
            sTmp2[nb * TMP_STRIDE + a2]       = make_float2(t0x, t0y);
            sTmp2[(nb + 8) * TMP_STRIDE + a2] = make_float2(t1x, t1y);
        }
        __syncthreads();

        // phase 2: out[n][xo] = gamma * sum_a tmp[n][a] * Fx[xo][a]
        {
            const float2* tv = &sTmp2[pn * TMP_STRIDE];
            const float2* fv = reinterpret_cast<const float2*>(&sFxp[pxo * FX_STRIDE]);
            float s = 0.f;
            #pragma unroll 8
            for (int q = 0; q < 32; q++) {
                float2 t = tv[q];
                float2 f = fv[q];
                s += t.x * f.x + t.y * f.y;
            }
            s *= gam;
            int idx = b * IN_ + c * (NF_ * NF_) + pn * NF_ + pxo;
            __nv_bfloat16 hi, lo;
            splitf(s, hi, lo);
            g_r_hi[idx] = hi;
            g_r_lo[idx] = lo;
        }
    }
}

// ---------------- HMMA gate GEMM + fused LSTM epilogue (round-7 config) ----------------
#define KCHUNKS 28
#define LDS_ROW 144
#define A_HI 0
#define A_LO 18432
#define W_HI 36864
#define W_LO 73728
#define STAGE_BYTES 110592
#define GEMM_SMEM (2 * STAGE_BYTES)

__device__ __forceinline__ void load_chunk_async(int kt, int m0, int n0, int tid,
                                                 uint32_t stage) {
    const __nv_bfloat16 *Ah, *Al, *Wh, *Wl;
    int ldA, kk;
    if (kt < 12) { Ah = g_r_hi; Al = g_r_lo; Wh = g_Wih_hi; Wl = g_Wih_lo; ldA = IN_; kk = kt * 64; }
    else         { Ah = g_h_hi; Al = g_h_lo; Wh = g_Whh_hi; Wl = g_Whh_lo; ldA = HD_; kk = (kt - 12) * 64; }

    if (tid < 256) {
        int row = tid >> 1, hf = tid & 1;
        const __nv_bfloat16* sh = Ah + (size_t)(m0 + row) * ldA + kk + hf * 32;
        const __nv_bfloat16* sl = Al + (size_t)(m0 + row) * ldA + kk + hf * 32;
        uint32_t d = stage + A_HI + row * LDS_ROW + hf * 64;
        #pragma unroll
        for (int i = 0; i < 4; i++) {
            cpa16(d + i * 16, sh + i * 8);
            cpa16(d + (A_LO - A_HI) + i * 16, sl + i * 8);
        }
    } else {
        int t = tid - 256;
        const __nv_bfloat16* sh = Wh + (size_t)(n0 + t) * ldA + kk;
        const __nv_bfloat16* sl = Wl + (size_t)(n0 + t) * ldA + kk;
        uint32_t d = stage + W_HI + t * LDS_ROW;
        #pragma unroll
        for (int i = 0; i < 8; i++) {
            cpa16(d + i * 16, sh + i * 8);
            cpa16(d + (W_LO - W_HI) + i * 16, sl + i * 8);
        }
    }
}

__global__ __launch_bounds__(512, 1)
void gate_gemm_lstm(float* __restrict__ c_state, float* __restrict__ h_state) {
    extern __shared__ char smem[];
    const uint32_t sb = smem_to_u32(smem);
    const int tid = threadIdx.x;
    const int lane = tid & 31;
    const int wid = tid >> 5;
    const int warp_m = wid >> 2;     // 0..3
    const int warp_n = wid & 3;      // 0..3 (= gate index)
    const int nb = blockIdx.x;
    const int n0 = nb * 256;
    const int m0 = blockIdx.y * 128;

    float acc[2][8][4];
    #pragma unroll
    for (int i = 0; i < 2; i++)
        #pragma unroll
        for (int j = 0; j < 8; j++)
            #pragma unroll
            for (int k = 0; k < 4; k++) acc[i][j][k] = 0.f;

    load_chunk_async(0, m0, n0, tid, sb);
    CP_COMMIT();

    for (int kt = 0; kt < KCHUNKS; kt++) {
        const uint32_t sA = sb + (kt & 1) * STAGE_BYTES;
        if (kt + 1 < KCHUNKS) {
            load_chunk_async(kt + 1, m0, n0, tid, sb + ((kt + 1) & 1) * STAGE_BYTES);
            CP_COMMIT();
            CP_WAIT(1);
        } else {
            CP_WAIT(0);
        }
        __syncthreads();

        #pragma unroll
        for (int k16 = 0; k16 < 4; k16++) {
            uint32_t ah[2][4], al[2][4];
            #pragma unroll
            for (int mt = 0; mt < 2; mt++) {
                uint32_t row = warp_m * 32 + mt * 16 + (lane & 15);
                uint32_t ad = sA + A_HI + row * LDS_ROW + k16 * 32 + ((lane >> 4) * 16);
                ldsm4(ah[mt], ad);
                ldsm4(al[mt], ad + (A_LO - A_HI));
            }
            const uint32_t rown = warp_n * 64 + (lane & 7) + ((lane >> 4) * 8);
            const uint32_t coff = k16 * 32 + (((lane >> 3) & 1) * 16);
            #pragma unroll
            for (int g = 0; g < 4; g++) {
                uint32_t t4[4];
                ldsm4(t4, sA + W_HI + (rown + g * 16) * LDS_ROW + coff);
                #pragma unroll
                for (int mt = 0; mt < 2; mt++) {
                    mma_bf16(acc[mt][2 * g],     ah[mt], t4);
                    mma_bf16(acc[mt][2 * g + 1], ah[mt], t4 + 2);
                    mma_bf16(acc[mt][2 * g],     al[mt], t4);
                    mma_bf16(acc[mt][2 * g + 1], al[mt], t4 + 2);
                }
            }
            #pragma unroll
            for (int g = 0; g < 4; g++) {
                uint32_t t4[4];
                ldsm4(t4, sA + W_LO + (rown + g * 16) * LDS_ROW + coff);
                #pragma unroll
                for (int mt = 0; mt < 2; mt++) {
                    mma_bf16(acc[mt][2 * g],     ah[mt], t4);
                    mma_bf16(acc[mt][2 * g + 1], ah[mt], t4 + 2);
                }
            }
        }
        __syncthreads();
    }

    // ---- fused LSTM epilogue (fast-math intrinsics) ----
    float* stg = reinterpret_cast<float*>(smem);
    const int r0 = lane >> 2;
    const int c0 = (lane & 3) * 2;

    #pragma unroll
    for (int mt = 0; mt < 2; mt++) {
        #pragma unroll
        for (int nt = 0; nt < 8; nt++) {
            int scol = warp_n * 64 + nt * 8 + c0;
            int srow = warp_m * 16 + r0;
            stg[srow * 256 + scol]           = acc[mt][nt][0];
            stg[srow * 256 + scol + 1]       = acc[mt][nt][1];
            stg[(srow + 8) * 256 + scol]     = acc[mt][nt][2];
            stg[(srow + 8) * 256 + scol + 1] = acc[mt][nt][3];
        }
        __syncthreads();

        #pragma unroll
        for (int t = 0; t < 8; t++) {
            int idx = t * 512 + tid;
            int sr = idx >> 6;
            int jw = idx & 63;
            int m  = m0 + (sr >> 4) * 32 + mt * 16 + (sr & 15);
            int j  = nb * 64 + jw;

            float ig = stg[sr * 256 + jw]        + g_bias[n0 + jw];
            float fg = stg[sr * 256 + 64 + jw]   + g_bias[n0 + 64 + jw];
            float gg = stg[sr * 256 + 128 + jw]  + g_bias[n0 + 128 + jw];
            float og = stg[sr * 256 + 192 + jw]  + g_bias[n0 + 192 + jw];

            int ci = m * HD_ + j;
            float cn = sigm_f(fg) * c_state[ci] + sigm_f(ig) * tanh_f(gg);
            c_state[ci] = cn;
            float hn = sigm_f(og) * tanh_f(cn);
            h_state[ci] = hn;
            __nv_bfloat16 hi, lo;
            splitf(hn, hi, lo);
            g_h_hi[ci] = hi;
            g_h_lo[ci] = lo;
        }
        __syncthreads();
    }
}

// ---------------- zero h and c (+ splits) ----------------
__global__ void zero_hc_kernel() {
    int i = blockIdx.x * blockDim.x + threadIdx.x;
    if (i < BT_ * HD_) {
        g_h[i] = 0.f; g_c[i] = 0.f;
        g_h_hi[i] = __float2bfloat16(0.f);
        g_h_lo[i] = __float2bfloat16(0.f);
    }
}

// ---------------- SIMT GEMM (fc0 only) ----------------
template <bool RELU>
__global__ __launch_bounds__(256, 2)
void gemm_nt(const float* __restrict__ A0, int K0, const float* __restrict__ W0,
             const float* __restrict__ bias0,
             float* __restrict__ C, int M, int Nn) {
    __shared__ float As[16][128];
    __shared__ float Bs[16][128];

    const int tid = threadIdx.x;
    const int m0  = blockIdx.y * 128;
    const int n0  = blockIdx.x * 128;
    const int tx  = tid & 15;
    const int ty  = tid >> 4;
    const int lrow = tid >> 1;
    const int lq   = (tid & 1) * 2;

    float acc[8][8];
    #pragma unroll
    for (int i = 0; i < 8; i++)
        #pragma unroll
        for (int j = 0; j < 8; j++) acc[i][j] = 0.f;

    for (int kt = 0; kt < K0; kt += 16) {
        #pragma unroll
        for (int qq = 0; qq < 2; qq++) {
            int q = lq + qq;
            float4 va = *reinterpret_cast<const float4*>(A0 + (m0 + lrow) * K0 + kt + q * 4);
            As[q * 4 + 0][lrow] = va.x;
            As[q * 4 + 1][lrow] = va.y;
            As[q * 4 + 2][lrow] = va.z;
            As[q * 4 + 3][lrow] = va.w;
            float4 vb = *reinterpret_cast<const float4*>(W0 + (n0 + lrow) * K0 + kt + q * 4);
            Bs[q * 4 + 0][lrow] = vb.x;
            Bs[q * 4 + 1][lrow] = vb.y;
            Bs[q * 4 + 2][lrow] = vb.z;
            Bs[q * 4 + 3][lrow] = vb.w;
        }
        __syncthreads();

        #pragma unroll
        for (int k = 0; k < 16; k++) {
            float ra[8], rb[8];
            #pragma unroll
            for (int i = 0; i < 8; i++) ra[i] = As[k][ty * 8 + i];
            #pragma unroll
            for (int j = 0; j < 8; j++) rb[j] = Bs[k][tx * 8 + j];
            #pragma unroll
            for (int i = 0; i < 8; i++)
                #pragma unroll
                for (int j = 0; j < 8; j++) acc[i][j] += ra[i] * rb[j];
        }
        __syncthreads();
    }

    #pragma unroll
    for (int i = 0; i < 8; i++) {
        int m = m0 + ty * 8 + i;
        #pragma unroll
        for (int jv = 0; jv < 2; jv++) {
            int n = n0 + tx * 8 + jv * 4;
            float4 v;
            float* vp = &v.x;
            #pragma unroll
            for (int u = 0; u < 4; u++) {
                float t = acc[i][jv * 4 + u] + bias0[n + u];
                if (RELU) t = fmaxf(t, 0.f);
                vp[u] = t;
            }
            *reinterpret_cast<float4*>(C + (size_t)m * Nn + n) = v;
        }
    }
}

// ---------------- final small fc ----------------
__global__ void fc_kernel(const float* __restrict__ t,
                          const float* __restrict__ W_fc,
                          const float* __restrict__ b_fc,
                          float* __restrict__ out) {
    int b    = blockIdx.x;
    int w    = threadIdx.x >> 5;
    int lane = threadIdx.x & 31;
    const float* tb = t + b * HD_;
    const float* wr = W_fc + w * HD_;
    float s = 0.f;
    for (int k = lane; k < HD_; k += 32) s += tb[k] * wr[k];
    #pragma unroll
    for (int off = 16; off; off >>= 1) s += __shfl_down_sync(0xffffffffu, s, off);
    if (lane == 0) out[b * 10 + w] = s + b_fc[w];
}

// ---------------- host launch ----------------
extern "C" void kernel_launch(void* const* d_in, const int* in_sizes, int n_in,
                              void* d_out, int out_size) {
    const float* x     = (const float*)d_in[0];
    const float* W_att = (const float*)d_in[1];
    const float* b_att = (const float*)d_in[2];
    const float* W_ih  = (const float*)d_in[3];
    const float* W_hh  = (const float*)d_in[4];
    const float* b_ih  = (const float*)d_in[5];
    const float* b_hh  = (const float*)d_in[6];
    const float* W_fc0 = (const float*)d_in[7];
    const float* b_fc0 = (const float*)d_in[8];
    const float* W_fc  = (const float*)d_in[9];
    const float* b_fc  = (const float*)d_in[10];
    float* out = (float*)d_out;

    static float *p_h = nullptr, *p_c, *p_t;
    static bool attr_done = false;
    if (!p_h) {
        cudaGetSymbolAddress((void**)&p_h, g_h);
        cudaGetSymbolAddress((void**)&p_c, g_c);
        cudaGetSymbolAddress((void**)&p_t, g_t);
    }
    if (!attr_done) {
        cudaFuncSetAttribute(gate_gemm_lstm,
                             cudaFuncAttributeMaxDynamicSharedMemorySize, GEMM_SMEM);
        attr_done = true;
    }

    {
        const int total = GATE_ * IN_ + GATE_ * HD_ + GATE_;
        prep_kernel<<<(total + 255) / 256, 256>>>(W_ih, W_hh, b_ih, b_hh);
    }

    zero_hc_kernel<<<(BT_ * HD_ + 255) / 256, 256>>>();

    for (int step = 0; step < TSTEPS_; step++) {
        att_glimpse_kernel<<<BT_, 256>>>(x, p_h, W_att, b_att);
        gate_gemm_lstm<<<dim3(GATE_ / 256, BT_ / 128), 512, GEMM_SMEM>>>(p_c, p_h);
    }

    gemm_nt<true><<<dim3(HD_ / 128, BT_ / 128), 256>>>(p_h, HD_, W_fc0, b_fc0, p_t, BT_, HD_);

    fc_kernel<<<BT_, 320>>>(p_t, W_fc, b_fc, out);
}

// round 17
// speedup vs baseline: 1.0750x; 1.0200x over previous
#include <cuda_runtime.h>
#include <cuda_bf16.h>
#include <math.h>
#include <stdint.h>

// ---------------- problem constants ----------------
#define BT_   1024
#define CH_   3
#define AW_   64
#define BH_   64
#define NF_   16
#define HD_   1024
#define IN_   768
#define GATE_ 4096
#define TSTEPS_ 16

// ---------------- persistent scratch ----------------
__device__ float g_h[BT_ * HD_];
__device__ float g_c[BT_ * HD_];
__device__ float g_t[BT_ * HD_];

// pre-split bf16 activations
__device__ __nv_bfloat16 g_r_hi[BT_ * IN_];
__device__ __nv_bfloat16 g_r_lo[BT_ * IN_];
__device__ __nv_bfloat16 g_h_hi[BT_ * HD_];
__device__ __nv_bfloat16 g_h_lo[BT_ * HD_];

// pre-split bf16 weights (gate-interleaved row order) + fused bias
__device__ __nv_bfloat16 g_Wih_hi[GATE_ * IN_];
__device__ __nv_bfloat16 g_Wih_lo[GATE_ * IN_];
__device__ __nv_bfloat16 g_Whh_hi[GATE_ * HD_];
__device__ __nv_bfloat16 g_Whh_lo[GATE_ * HD_];
__device__ float g_bias[GATE_];
// fc0 split weights
__device__ __nv_bfloat16 g_Wfc0_hi[HD_ * HD_];
__device__ __nv_bfloat16 g_Wfc0_lo[HD_ * HD_];

// ---------------- helpers ----------------
__device__ __forceinline__ uint32_t smem_to_u32(const void* p) {
    uint32_t a;
    asm("{ .reg .u64 t; cvta.to.shared.u64 t, %1; cvt.u32.u64 %0, t; }" : "=r"(a) : "l"(p));
    return a;
}
__device__ __forceinline__ void ldsm4(uint32_t* r, uint32_t addr) {
    asm volatile("ldmatrix.sync.aligned.m8n8.x4.shared.b16 {%0,%1,%2,%3}, [%4];"
        : "=r"(r[0]), "=r"(r[1]), "=r"(r[2]), "=r"(r[3]) : "r"(addr));
}
__device__ __forceinline__ void mma_bf16(float* d, const uint32_t* a, const uint32_t* b) {
    asm volatile("mma.sync.aligned.m16n8k16.row.col.f32.bf16.bf16.f32 "
        "{%0,%1,%2,%3}, {%4,%5,%6,%7}, {%8,%9}, {%0,%1,%2,%3};"
        : "+f"(d[0]), "+f"(d[1]), "+f"(d[2]), "+f"(d[3])
        : "r"(a[0]), "r"(a[1]), "r"(a[2]), "r"(a[3]), "r"(b[0]), "r"(b[1]));
}
__device__ __forceinline__ void cpa16(uint32_t dst, const void* src) {
    asm volatile("cp.async.cg.shared.global [%0], [%1], 16;" :: "r"(dst), "l"(src));
}
#define CP_COMMIT() asm volatile("cp.async.commit_group;")
#define CP_WAIT(n)  asm volatile("cp.async.wait_group %0;" :: "n"(n))

__device__ __forceinline__ void splitf(float v, __nv_bfloat16& hi, __nv_bfloat16& lo) {
    hi = __float2bfloat16_rn(v);
    lo = __float2bfloat16_rn(v - __bfloat162float(hi));
}
__device__ __forceinline__ float sigm_f(float v) { return 1.f / (1.f + __expf(-v)); }
__device__ __forceinline__ float tanh_f(float v) { return 2.f / (1.f + __expf(-2.f * v)) - 1.f; }

// row reorder: orig row rho -> blk*256 + gate*64 + jw
__device__ __forceinline__ int remap_row(int rho) {
    int gate = rho >> 10;
    int rem  = rho & 1023;
    return (rem >> 6) * 256 + gate * 64 + (rem & 63);
}

// ---------------- weight prep (split + reorder + fc0) ----------------
__global__ void prep_kernel(const float* __restrict__ W_ih, const float* __restrict__ W_hh,
                            const float* __restrict__ b_ih, const float* __restrict__ b_hh,
                            const float* __restrict__ W_fc0) {
    const int T1 = GATE_ * IN_;
    const int T2 = GATE_ * HD_;
    const int T3 = HD_ * HD_;
    int i = blockIdx.x * blockDim.x + threadIdx.x;
    if (i < T1) {
        int rho = i / IN_, k = i - rho * IN_;
        int ni = remap_row(rho) * IN_ + k;
        splitf(W_ih[i], g_Wih_hi[ni], g_Wih_lo[ni]);
    } else if (i < T1 + T2) {
        int j = i - T1;
        int rho = j >> 10, k = j & 1023;
        int ni = (remap_row(rho) << 10) + k;
        splitf(W_hh[j], g_Whh_hi[ni], g_Whh_lo[ni]);
    } else if (i < T1 + T2 + GATE_) {
        int rho = i - T1 - T2;
        g_bias[remap_row(rho)] = b_ih[rho] + b_hh[rho];
    } else if (i < T1 + T2 + GATE_ + T3) {
        int j = i - T1 - T2 - GATE_;
        splitf(W_fc0[j], g_Wfc0_hi[j], g_Wfc0_lo[j]);
    }
}

// ---------------- fused att + filterbank + glimpse (round-12 exact) ----------------
#define FX_STRIDE 66
#define TMP_STRIDE 33
__global__ __launch_bounds__(256)
void att_glimpse_kernel(const float* __restrict__ x,
                        const float* __restrict__ h,
                        const float* __restrict__ W_att,
                        const float* __restrict__ b_att) {
    const int b   = blockIdx.x;
    const int tid = threadIdx.x;
    const int lane = tid & 31;
    const int wid = tid >> 5;

    __shared__ float  sFy[NF_ * BH_];
    __shared__ float  sFxp[NF_ * FX_STRIDE];
    __shared__ float2 sImg2[BH_ * 32];
    __shared__ float2 sTmp2[NF_ * TMP_STRIDE];
    __shared__ float  red[5][8];
    __shared__ float  params[5];
    __shared__ float  rnorm[16];

    {
        float a0 = 0.f, a1 = 0.f, a2 = 0.f, a3 = 0.f, a4 = 0.f;
        const float* hb = h + b * HD_;
        for (int k = tid; k < HD_; k += 256) {
            float hv = hb[k];
            a0 += hv * W_att[0 * HD_ + k];
            a1 += hv * W_att[1 * HD_ + k];
            a2 += hv * W_att[2 * HD_ + k];
            a3 += hv * W_att[3 * HD_ + k];
            a4 += hv * W_att[4 * HD_ + k];
        }
        #pragma unroll
        for (int off = 16; off; off >>= 1) {
            a0 += __shfl_down_sync(0xffffffffu, a0, off);
            a1 += __shfl_down_sync(0xffffffffu, a1, off);
            a2 += __shfl_down_sync(0xffffffffu, a2, off);
            a3 += __shfl_down_sync(0xffffffffu, a3, off);
            a4 += __shfl_down_sync(0xffffffffu, a4, off);
        }
        if (lane == 0) {
            red[0][wid] = a0; red[1][wid] = a1; red[2][wid] = a2;
            red[3][wid] = a3; red[4][wid] = a4;
        }
        __syncthreads();
        if (tid < 5) {
            float s = 0.f;
            #pragma unroll
            for (int w = 0; w < 8; w++) s += red[tid][w];
            params[tid] = s + b_att[tid];
        }
        __syncthreads();
    }

    const float gx     = 32.5f * (params[0] + 1.0f);
    const float gy     = 32.5f * (params[1] + 1.0f);
    const float sigma2 = expf(params[2]);
    const float delta  = (63.0f / 15.0f) * expf(params[3]);
    const float gam    = expf(params[4]);
    const float inv2s  = 1.0f / (2.0f * sigma2);

    for (int idx = tid; idx < NF_ * AW_; idx += 256) {
        int i = idx >> 6, a = idx & 63;
        float mu = gx + ((float)i - 8.5f) * delta;
        float d  = (float)a - mu;
        sFxp[i * FX_STRIDE + a] = __expf(-d * d * inv2s);
    }
    __syncthreads();
    if (tid < 16) {
        float s = 0.f;
        for (int a = 0; a < 64; a++) s += sFxp[tid * FX_STRIDE + a];
        rnorm[tid] = 1.0f / (s + 1e-8f);
    }
    __syncthreads();
    for (int idx = tid; idx < NF_ * AW_; idx += 256) {
        int i = idx >> 6, a = idx & 63;
        sFxp[i * FX_STRIDE + a] *= rnorm[i];
    }
    __syncthreads();

    for (int idx = tid; idx < NF_ * BH_; idx += 256) {
        int i = idx >> 6, a = idx & 63;
        float mu = gy + ((float)i - 8.5f) * delta;
        float d  = (float)a - mu;
        sFy[idx] = __expf(-d * d * inv2s);
    }
    __syncthreads();
    if (tid < 16) {
        float s = 0.f;
        for (int a = 0; a < 64; a++) s += sFy[tid * 64 + a];
        rnorm[tid] = 1.0f / (s + 1e-8f);
    }
    __syncthreads();
    for (int idx = tid; idx < NF_ * BH_; idx += 256) {
        sFy[idx] *= rnorm[idx >> 6];
    }

    const int a2 = tid & 31;
    const int nb = tid >> 5;
    const int pn = tid >> 4;
    const int pxo = tid & 15;

    for (int c = 0; c < CH_; c++) {
        __syncthreads();
        const float* xc = x + ((size_t)(b * CH_ + c)) * (BH_ * AW_);
        for (int idx = tid; idx < BH_ * 32; idx += 256)
            sImg2[idx] = reinterpret_cast<const float2*>(xc)[idx];
        __syncthreads();

        {
            float t0x = 0.f, t0y = 0.f, t1x = 0.f, t1y = 0.f;
            const float* fy0 = &sFy[nb * BH_];
            const float* fy1 = &sFy[(nb + 8) * BH_];
            #pragma unroll 8
            for (int y = 0; y < BH_; y++) {
                float2 iv = sImg2[y * 32 + a2];
                float f0 = fy0[y];
                float f1 = fy1[y];
                t0x += f0 * iv.x; t0y += f0 * iv.y;
                t1x += f1 * iv.x; t1y += f1 * iv.y;
            }
            sTmp2[nb * TMP_STRIDE + a2]       = make_float2(t0x, t0y);
            sTmp2[(nb + 8) * TMP_STRIDE + a2] = make_float2(t1x, t1y);
        }
        __syncthreads();

        {
            const float2* tv = &sTmp2[pn * TMP_STRIDE];
            const float2* fv = reinterpret_cast<const float2*>(&sFxp[pxo * FX_STRIDE]);
            float s = 0.f;
            #pragma unroll 8
            for (int q = 0; q < 32; q++) {
                float2 t = tv[q];
                float2 f = fv[q];
                s += t.x * f.x + t.y * f.y;
            }
            s *= gam;
            int idx = b * IN_ + c * (NF_ * NF_) + pn * NF_ + pxo;
            __nv_bfloat16 hi, lo;
            splitf(s, hi, lo);
            g_r_hi[idx] = hi;
            g_r_lo[idx] = lo;
        }
    }
}

// ---------------- HMMA gate GEMM + fused LSTM epilogue ----------------
#define KCHUNKS 28
#define LDS_ROW 144
#define A_HI 0
#define A_LO 18432
#define W_HI 36864
#define W_LO 73728
#define STAGE_BYTES 110592
#define GEMM_SMEM (2 * STAGE_BYTES)

__device__ __forceinline__ void load_chunk_async(int kt, int m0, int n0, int tid,
                                                 uint32_t stage) {
    const __nv_bfloat16 *Ah, *Al, *Wh, *Wl;
    int ldA, kk;
    if (kt < 12) { Ah = g_r_hi; Al = g_r_lo; Wh = g_Wih_hi; Wl = g_Wih_lo; ldA = IN_; kk = kt * 64; }
    else         { Ah = g_h_hi; Al = g_h_lo; Wh = g_Whh_hi; Wl = g_Whh_lo; ldA = HD_; kk = (kt - 12) * 64; }

    if (tid < 256) {
        int row = tid >> 1, hf = tid & 1;
        const __nv_bfloat16* sh = Ah + (size_t)(m0 + row) * ldA + kk + hf * 32;
        const __nv_bfloat16* sl = Al + (size_t)(m0 + row) * ldA + kk + hf * 32;
        uint32_t d = stage + A_HI + row * LDS_ROW + hf * 64;
        #pragma unroll
        for (int i = 0; i < 4; i++) {
            cpa16(d + i * 16, sh + i * 8);
            cpa16(d + (A_LO - A_HI) + i * 16, sl + i * 8);
        }
    } else {
        int t = tid - 256;
        const __nv_bfloat16* sh = Wh + (size_t)(n0 + t) * ldA + kk;
        const __nv_bfloat16* sl = Wl + (size_t)(n0 + t) * ldA + kk;
        uint32_t d = stage + W_HI + t * LDS_ROW;
        #pragma unroll
        for (int i = 0; i < 8; i++) {
            cpa16(d + i * 16, sh + i * 8);
            cpa16(d + (W_LO - W_HI) + i * 16, sl + i * 8);
        }
    }
}

__global__ __launch_bounds__(512, 1)
void gate_gemm_lstm(float* __restrict__ c_state, float* __restrict__ h_state) {
    extern __shared__ char smem[];
    const uint32_t sb = smem_to_u32(smem);
    const int tid = threadIdx.x;
    const int lane = tid & 31;
    const int wid = tid >> 5;
    const int warp_m = wid >> 2;
    const int warp_n = wid & 3;
    const int nb = blockIdx.x;
    const int n0 = nb * 256;
    const int m0 = blockIdx.y * 128;

    float acc[2][8][4];
    #pragma unroll
    for (int i = 0; i < 2; i++)
        #pragma unroll
        for (int j = 0; j < 8; j++)
            #pragma unroll
            for (int k = 0; k < 4; k++) acc[i][j][k] = 0.f;

    load_chunk_async(0, m0, n0, tid, sb);
    CP_COMMIT();

    for (int kt = 0; kt < KCHUNKS; kt++) {
        const uint32_t sA = sb + (kt & 1) * STAGE_BYTES;
        if (kt + 1 < KCHUNKS) {
            load_chunk_async(kt + 1, m0, n0, tid, sb + ((kt + 1) & 1) * STAGE_BYTES);
            CP_COMMIT();
            CP_WAIT(1);
        } else {
            CP_WAIT(0);
        }
        __syncthreads();

        #pragma unroll
        for (int k16 = 0; k16 < 4; k16++) {
            uint32_t ah[2][4], al[2][4];
            #pragma unroll
            for (int mt = 0; mt < 2; mt++) {
                uint32_t row = warp_m * 32 + mt * 16 + (lane & 15);
                uint32_t ad = sA + A_HI + row * LDS_ROW + k16 * 32 + ((lane >> 4) * 16);
                ldsm4(ah[mt], ad);
                ldsm4(al[mt], ad + (A_LO - A_HI));
            }
            const uint32_t rown = warp_n * 64 + (lane & 7) + ((lane >> 4) * 8);
            const uint32_t coff = k16 * 32 + (((lane >> 3) & 1) * 16);
            #pragma unroll
            for (int g = 0; g < 4; g++) {
                uint32_t t4[4];
                ldsm4(t4, sA + W_HI + (rown + g * 16) * LDS_ROW + coff);
                #pragma unroll
                for (int mt = 0; mt < 2; mt++) {
                    mma_bf16(acc[mt][2 * g],     ah[mt], t4);
                    mma_bf16(acc[mt][2 * g + 1], ah[mt], t4 + 2);
                    mma_bf16(acc[mt][2 * g],     al[mt], t4);
                    mma_bf16(acc[mt][2 * g + 1], al[mt], t4 + 2);
                }
            }
            #pragma unroll
            for (int g = 0; g < 4; g++) {
                uint32_t t4[4];
                ldsm4(t4, sA + W_LO + (rown + g * 16) * LDS_ROW + coff);
                #pragma unroll
                for (int mt = 0; mt < 2; mt++) {
                    mma_bf16(acc[mt][2 * g],     ah[mt], t4);
                    mma_bf16(acc[mt][2 * g + 1], ah[mt], t4 + 2);
                }
            }
        }
        __syncthreads();
    }

    // ---- fused LSTM epilogue (fast-math intrinsics) ----
    float* stg = reinterpret_cast<float*>(smem);
    const int r0 = lane >> 2;
    const int c0 = (lane & 3) * 2;

    #pragma unroll
    for (int mt = 0; mt < 2; mt++) {
        #pragma unroll
        for (int nt = 0; nt < 8; nt++) {
            int scol = warp_n * 64 + nt * 8 + c0;
            int srow = warp_m * 16 + r0;
            stg[srow * 256 + scol]           = acc[mt][nt][0];
            stg[srow * 256 + scol + 1]       = acc[mt][nt][1];
            stg[(srow + 8) * 256 + scol]     = acc[mt][nt][2];
            stg[(srow + 8) * 256 + scol + 1] = acc[mt][nt][3];
        }
        __syncthreads();

        #pragma unroll
        for (int t = 0; t < 8; t++) {
            int idx = t * 512 + tid;
            int sr = idx >> 6;
            int jw = idx & 63;
            int m  = m0 + (sr >> 4) * 32 + mt * 16 + (sr & 15);
            int j  = nb * 64 + jw;

            float ig = stg[sr * 256 + jw]        + g_bias[n0 + jw];
            float fg = stg[sr * 256 + 64 + jw]   + g_bias[n0 + 64 + jw];
            float gg = stg[sr * 256 + 128 + jw]  + g_bias[n0 + 128 + jw];
            float og = stg[sr * 256 + 192 + jw]  + g_bias[n0 + 192 + jw];

            int ci = m * HD_ + j;
            float cn = sigm_f(fg) * c_state[ci] + sigm_f(ig) * tanh_f(gg);
            c_state[ci] = cn;
            float hn = sigm_f(og) * tanh_f(cn);
            h_state[ci] = hn;
            __nv_bfloat16 hi, lo;
            splitf(hn, hi, lo);
            g_h_hi[ci] = hi;
            g_h_lo[ci] = lo;
        }
        __syncthreads();
    }
}

// ---------------- fc0 MMA GEMM: t = relu(h @ W_fc0^T + b_fc0) ----------------
// CTA 128M x 128N, grid (8,8) = 64 CTAs, 512 threads, warp tile 32x32, K chunk 64.
#define F_KCH 16
#define F_A_HI 0
#define F_A_LO 18432
#define F_W_HI 36864
#define F_W_LO 55296
#define F_STAGE 73728
#define FC0_SMEM (2 * F_STAGE)

__device__ __forceinline__ void loadF(int kt, int m0, int n0, int tid, uint32_t stage) {
    int kk = kt * 64;
    if (tid < 256) {
        int row = tid >> 1, hf = tid & 1;
        const __nv_bfloat16* sh = g_h_hi + (size_t)(m0 + row) * HD_ + kk + hf * 32;
        const __nv_bfloat16* sl = g_h_lo + (size_t)(m0 + row) * HD_ + kk + hf * 32;
        uint32_t d = stage + F_A_HI + row * LDS_ROW + hf * 64;
        #pragma unroll
        for (int i = 0; i < 4; i++) {
            cpa16(d + i * 16, sh + i * 8);
            cpa16(d + (F_A_LO - F_A_HI) + i * 16, sl + i * 8);
        }
    } else if (tid < 384) {
        int t = tid - 256;
        const __nv_bfloat16* sh = g_Wfc0_hi + (size_t)(n0 + t) * HD_ + kk;
        const __nv_bfloat16* sl = g_Wfc0_lo + (size_t)(n0 + t) * HD_ + kk;
        uint32_t d = stage + F_W_HI + t * LDS_ROW;
        #pragma unroll
        for (int i = 0; i < 8; i++) {
            cpa16(d + i * 16, sh + i * 8);
            cpa16(d + (F_W_LO - F_W_HI) + i * 16, sl + i * 8);
        }
    }
}

__global__ __launch_bounds__(512, 1)
void fc0_gemm(const float* __restrict__ bias0) {
    extern __shared__ char smem[];
    const uint32_t sb = smem_to_u32(smem);
    const int tid = threadIdx.x;
    const int lane = tid & 31;
    const int wid = tid >> 5;
    const int warp_m = wid >> 2;     // 0..3
    const int warp_n = wid & 3;      // 0..3
    const int n0 = blockIdx.x * 128;
    const int m0 = blockIdx.y * 128;

    float acc[2][4][4];
    #pragma unroll
    for (int i = 0; i < 2; i++)
        #pragma unroll
        for (int j = 0; j < 4; j++)
            #pragma unroll
            for (int k = 0; k < 4; k++) acc[i][j][k] = 0.f;

    loadF(0, m0, n0, tid, sb);
    CP_COMMIT();

    for (int kt = 0; kt < F_KCH; kt++) {
        const uint32_t sA = sb + (kt & 1) * F_STAGE;
        if (kt + 1 < F_KCH) {
            loadF(kt + 1, m0, n0, tid, sb + ((kt + 1) & 1) * F_STAGE);
            CP_COMMIT();
            CP_WAIT(1);
        } else {
            CP_WAIT(0);
        }
        __syncthreads();

        #pragma unroll
        for (int k16 = 0; k16 < 4; k16++) {
            uint32_t ah[2][4], al[2][4];
            #pragma unroll
            for (int mt = 0; mt < 2; mt++) {
                uint32_t row = warp_m * 32 + mt * 16 + (lane & 15);
                uint32_t ad = sA + F_A_HI + row * LDS_ROW + k16 * 32 + ((lane >> 4) * 16);
                ldsm4(ah[mt], ad);
                ldsm4(al[mt], ad + (F_A_LO - F_A_HI));
            }
            const uint32_t rown = warp_n * 32 + (lane & 7) + ((lane >> 4) * 8);
            const uint32_t coff = k16 * 32 + (((lane >> 3) & 1) * 16);
            #pragma unroll
            for (int g = 0; g < 2; g++) {
                uint32_t t4[4];
                ldsm4(t4, sA + F_W_HI + (rown + g * 16) * LDS_ROW + coff);
                #pragma unroll
                for (int mt = 0; mt < 2; mt++) {
                    mma_bf16(acc[mt][2 * g],     ah[mt], t4);
                    mma_bf16(acc[mt][2 * g + 1], ah[mt], t4 + 2);
                    mma_bf16(acc[mt][2 * g],     al[mt], t4);
                    mma_bf16(acc[mt][2 * g + 1], al[mt], t4 + 2);
                }
            }
            #pragma unroll
            for (int g = 0; g < 2; g++) {
                uint32_t t4[4];
                ldsm4(t4, sA + F_W_LO + (rown + g * 16) * LDS_ROW + coff);
                #pragma unroll
                for (int mt = 0; mt < 2; mt++) {
                    mma_bf16(acc[mt][2 * g],     ah[mt], t4);
                    mma_bf16(acc[mt][2 * g + 1], ah[mt], t4 + 2);
                }
            }
        }
        __syncthreads();
    }

    // epilogue: bias + relu, direct stores to g_t
    #pragma unroll
    for (int mt = 0; mt < 2; mt++) {
        int row0 = m0 + warp_m * 32 + mt * 16 + (lane >> 2);
        #pragma unroll
        for (int nt = 0; nt < 4; nt++) {
            int col = n0 + warp_n * 32 + nt * 8 + (lane & 3) * 2;
            float2 bv = *reinterpret_cast<const float2*>(&bias0[col]);
            float2 v0 = make_float2(fmaxf(acc[mt][nt][0] + bv.x, 0.f),
                                    fmaxf(acc[mt][nt][1] + bv.y, 0.f));
            float2 v1 = make_float2(fmaxf(acc[mt][nt][2] + bv.x, 0.f),
                                    fmaxf(acc[mt][nt][3] + bv.y, 0.f));
            *reinterpret_cast<float2*>(&g_t[(size_t)row0 * HD_ + col]) = v0;
            *reinterpret_cast<float2*>(&g_t[(size_t)(row0 + 8) * HD_ + col]) = v1;
        }
    }
}

// ---------------- zero h and c (+ splits) ----------------
__global__ void zero_hc_kernel() {
    int i = blockIdx.x * blockDim.x + threadIdx.x;
    if (i < BT_ * HD_) {
        g_h[i] = 0.f; g_c[i] = 0.f;
        g_h_hi[i] = __float2bfloat16(0.f);
        g_h_lo[i] = __float2bfloat16(0.f);
    }
}

// ---------------- final small fc ----------------
__global__ void fc_kernel(const float* __restrict__ t,
                          const float* __restrict__ W_fc,
                          const float* __restrict__ b_fc,
                          float* __restrict__ out) {
    int b    = blockIdx.x;
    int w    = threadIdx.x >> 5;
    int lane = threadIdx.x & 31;
    const float* tb = t + b * HD_;
    const float* wr = W_fc + w * HD_;
    float s = 0.f;
    for (int k = lane; k < HD_; k += 32) s += tb[k] * wr[k];
    #pragma unroll
    for (int off = 16; off; off >>= 1) s += __shfl_down_sync(0xffffffffu, s, off);
    if (lane == 0) out[b * 10 + w] = s + b_fc[w];
}

// ---------------- host launch ----------------
extern "C" void kernel_launch(void* const* d_in, const int* in_sizes, int n_in,
                              void* d_out, int out_size) {
    const float* x     = (const float*)d_in[0];
    const float* W_att = (const float*)d_in[1];
    const float* b_att = (const float*)d_in[2];
    const float* W_ih  = (const float*)d_in[3];
    const float* W_hh  = (const float*)d_in[4];
    const float* b_ih  = (const float*)d_in[5];
    const float* b_hh  = (const float*)d_in[6];
    const float* W_fc0 = (const float*)d_in[7];
    const float* b_fc0 = (const float*)d_in[8];
    const float* W_fc  = (const float*)d_in[9];
    const float* b_fc  = (const float*)d_in[10];
    float* out = (float*)d_out;

    static float *p_h = nullptr, *p_c, *p_t;
    static bool attr_done = false;
    if (!p_h) {
        cudaGetSymbolAddress((void**)&p_h, g_h);
        cudaGetSymbolAddress((void**)&p_c, g_c);
        cudaGetSymbolAddress((void**)&p_t, g_t);
    }
    if (!attr_done) {
        cudaFuncSetAttribute(gate_gemm_lstm,
                             cudaFuncAttributeMaxDynamicSharedMemorySize, GEMM_SMEM);
        cudaFuncSetAttribute(fc0_gemm,
                             cudaFuncAttributeMaxDynamicSharedMemorySize, FC0_SMEM);
        attr_done = true;
    }

    {
        const int total = GATE_ * IN_ + GATE_ * HD_ + GATE_ + HD_ * HD_;
        prep_kernel<<<(total + 255) / 256, 256>>>(W_ih, W_hh, b_ih, b_hh, W_fc0);
    }

    zero_hc_kernel<<<(BT_ * HD_ + 255) / 256, 256>>>();

    for (int step = 0; step < TSTEPS_; step++) {
        att_glimpse_kernel<<<BT_, 256>>>(x, p_h, W_att, b_att);
        gate_gemm_lstm<<<dim3(GATE_ / 256, BT_ / 128), 512, GEMM_SMEM>>>(p_c, p_h);
    }

    fc0_gemm<<<dim3(HD_ / 128, BT_ / 128), 512, FC0_SMEM>>>(b_fc0);

    fc_kernel<<<BT_, 320>>>(p_t, W_fc, b_fc, out);
}